// round 8
// baseline (speedup 1.0000x reference)
#include <cuda_runtime.h>
#include <cuda_fp16.h>
#include <cstdint>

// ---------------------------------------------------------------------------
// SimpleGCNNet:  Y = P^2 * X * W^T + b      (single fused kernel)
//   X: (2048, 2000) fp32, W: (128, 2000), b: (128,) -> Y: (32, 64, 128)
// Grid 161: blocks 0..159: Zp[ks] = X[batch mt] @ W^T over k-slice of 400,
//           single-pass fp16 mma.sync m16n8k16; block 160: build P -> P2t.
// Per-batch counter (monotonic, mod-6 = 5 splits + build): the last arriver
// sums the 5 partials, applies P2 + bias, and writes Y for that batch.
// ---------------------------------------------------------------------------

#define NNODE 64
#define GM 2048
#define GK 2000
#define GH 128
#define KSPLIT 5
#define KSLICE 400           // 25 k-tiles of 16
#define NKT 25
#define MT 64
#define EPSW 1e-6f
#define ARRIVALS 6           // 5 k-split blocks + 1 build block

// dynamic smem: GEMM stage 2*9216=18432 ; build scratch ~17KB ;
// apply: P2s 16384 + Zs 32768 = 49152  -> request 49152
#define STAGE_BYTES 9216
#define SMEM_DYN_BYTES 49152

__device__ float g_P2t[NNODE * NNODE];    // transposed: [m][n]
__device__ float g_Zp[KSPLIT][GM * GH];
__device__ unsigned g_cnt[32];            // monotonic per-batch arrival counters

// ---- helpers --------------------------------------------------------------
__device__ __forceinline__ uint32_t smem_u32(const void* p) {
    uint32_t a;
    asm("{ .reg .u64 t; cvta.to.shared.u64 t, %1; cvt.u32.u64 %0, t; }"
        : "=r"(a) : "l"(p));
    return a;
}
__device__ __forceinline__ unsigned long long pack2(float lo, float hi) {
    unsigned long long r;
    asm("mov.b64 %0, {%1, %2};" : "=l"(r) : "f"(lo), "f"(hi));
    return r;
}
__device__ __forceinline__ unsigned long long fma2(unsigned long long a,
                                                   unsigned long long b,
                                                   unsigned long long c) {
    unsigned long long d;
    asm("fma.rn.f32x2 %0, %1, %2, %3;" : "=l"(d) : "l"(a), "l"(b), "l"(c));
    return d;
}
__device__ __forceinline__ float2 unpack2(unsigned long long v) {
    float2 f;
    asm("mov.b64 {%0, %1}, %2;" : "=f"(f.x), "=f"(f.y) : "l"(v));
    return f;
}
__device__ __forceinline__ void ldsm4(uint32_t* r, uint32_t addr) {
    asm volatile("ldmatrix.sync.aligned.m8n8.x4.shared.b16 {%0,%1,%2,%3}, [%4];"
                 : "=r"(r[0]), "=r"(r[1]), "=r"(r[2]), "=r"(r[3]) : "r"(addr));
}
__device__ __forceinline__ void mma_f16(float* c, const uint32_t* a,
                                        uint32_t b0, uint32_t b1) {
    asm volatile(
        "mma.sync.aligned.m16n8k16.row.col.f32.f16.f16.f32 "
        "{%0,%1,%2,%3}, {%4,%5,%6,%7}, {%8,%9}, {%0,%1,%2,%3};"
        : "+f"(c[0]), "+f"(c[1]), "+f"(c[2]), "+f"(c[3])
        : "r"(a[0]), "r"(a[1]), "r"(a[2]), "r"(a[3]), "r"(b0), "r"(b1));
}
__device__ __forceinline__ void cvt_h2(float4 v, uint32_t& h0, uint32_t& h1) {
    asm("cvt.rn.f16x2.f32 %0, %1, %2;" : "=r"(h0) : "f"(v.y), "f"(v.x));
    asm("cvt.rn.f16x2.f32 %0, %1, %2;" : "=r"(h1) : "f"(v.w), "f"(v.z));
}
__device__ __forceinline__ void sts2(uint32_t addr, uint32_t a, uint32_t b) {
    asm volatile("st.shared.v2.b32 [%0], {%1, %2};" :: "r"(addr), "r"(a), "r"(b)
                 : "memory");
}

// ---------------------------------------------------------------------------
// apply: Y[b] = P2 @ (sum_s Zp[s])[b] + bias   (one block, reuses dyn smem)
// ---------------------------------------------------------------------------
__device__ void apply_batch(char* dsm, int b, const float* __restrict__ bias,
                            float* __restrict__ y) {
    float* P2s = (float*)dsm;            // [m][n] 16 KB
    float* Zs  = (float*)(dsm + 16384);  // [m][h] 32 KB
    const int tid = threadIdx.x;

    __syncthreads();   // smem reuse guard
    for (int i = tid; i < NNODE * NNODE; i += 256) P2s[i] = g_P2t[i];
    for (int p = tid; p < 2048; p += 256) {
        int row = p >> 5;
        int c4 = (p & 31) * 4;
        const float* src = &g_Zp[0][((size_t)b * NNODE + row) * GH + c4];
        float4 s = *(const float4*)src;
#pragma unroll
        for (int si = 1; si < KSPLIT; si++) {
            float4 v = *(const float4*)(src + (size_t)si * GM * GH);
            s.x += v.x; s.y += v.y; s.z += v.z; s.w += v.w;
        }
        *(float4*)&Zs[row * GH + c4] = s;
    }
    __syncthreads();

    const int hp = tid & 63;          // h-pair 0..63
    const int n0 = (tid >> 6) * 16;   // 16 output rows per thread

    unsigned long long acc[16];
    float2 bv = *(const float2*)(bias + 2 * hp);
    unsigned long long bini = pack2(bv.x, bv.y);
#pragma unroll
    for (int i = 0; i < 16; i++) acc[i] = bini;

#pragma unroll 4
    for (int m = 0; m < NNODE; m++) {
        unsigned long long z = *(const unsigned long long*)&Zs[m * GH + 2 * hp];
#pragma unroll
        for (int j0 = 0; j0 < 16; j0 += 4) {
            float4 p4 = *(const float4*)&P2s[m * NNODE + n0 + j0];
            acc[j0 + 0] = fma2(pack2(p4.x, p4.x), z, acc[j0 + 0]);
            acc[j0 + 1] = fma2(pack2(p4.y, p4.y), z, acc[j0 + 1]);
            acc[j0 + 2] = fma2(pack2(p4.z, p4.z), z, acc[j0 + 2]);
            acc[j0 + 3] = fma2(pack2(p4.w, p4.w), z, acc[j0 + 3]);
        }
    }

#pragma unroll
    for (int i = 0; i < 16; i++) {
        float2 v = unpack2(acc[i]);
        *(float2*)&y[((size_t)b * NNODE + n0 + i) * GH + 2 * hp] = v;
    }
}

// ---------------------------------------------------------------------------
// build P -> P2t ; scratch in dynamic smem
// ---------------------------------------------------------------------------
__device__ void build_p2_body(char* dsm, const int* __restrict__ eiw,
                              const float* __restrict__ ew, int E) {
    float* P    = (float*)dsm;
    float* deg  = (float*)(dsm + 16384);
    float* dinv = (float*)(dsm + 16640);
    int*   flag = (int*)(dsm + 16896);
    const int tid = threadIdx.x;

    for (int i = tid; i < NNODE * NNODE; i += 256) P[i] = 0.0f;
    if (tid < NNODE) deg[tid] = 1.0f;   // self-loop weight 1.0
    if (tid == 0) *flag = 0;
    __syncthreads();

    // dtype detect: int64 little-endian values in [0,64) -> odd words == 0
    if (tid < 64) {
        if (eiw[2 * tid + 1] != 0) atomicOr(flag, 1);
    }
    __syncthreads();
    const bool is64 = (*flag == 0);
    const int stride = is64 ? 2 : 1;
    const int dst_base = is64 ? 2 * E : E;

    for (int e = tid; e < E; e += 256) {
        float w = ew[e];
        if (w <= 0.0f) w = EPSW;
        atomicAdd(&deg[eiw[dst_base + e * stride] & (NNODE - 1)], w);
    }
    __syncthreads();
    if (tid < NNODE) {
        float d = deg[tid];
        dinv[tid] = (d > 0.0f) ? rsqrtf(d) : 0.0f;
    }
    __syncthreads();
    for (int e = tid; e < E; e += 256) {
        float w = ew[e];
        if (w <= 0.0f) w = EPSW;
        int s = eiw[e * stride] & (NNODE - 1);
        int d = eiw[dst_base + e * stride] & (NNODE - 1);
        atomicAdd(&P[d * NNODE + s], dinv[s] * w * dinv[d]);
    }
    if (tid < NNODE) atomicAdd(&P[tid * NNODE + tid], dinv[tid] * dinv[tid]);
    __syncthreads();
    for (int i = tid; i < NNODE * NNODE; i += 256) {
        int r = i >> 6, c = i & 63;
        float acc = 0.0f;
#pragma unroll 16
        for (int m = 0; m < NNODE; m++) acc += P[r * NNODE + m] * P[m * NNODE + c];
        g_P2t[c * NNODE + r] = acc;     // transposed [m][n]
    }
}

// ---------------------------------------------------------------------------
// Fused kernel: GEMM partials + build + last-arriver P2 apply
// ---------------------------------------------------------------------------
__global__ __launch_bounds__(256) void fused_kernel(
    const float* __restrict__ X, const float* __restrict__ W,
    const int* __restrict__ eiw, const float* __restrict__ ew, int E,
    const float* __restrict__ bias, float* __restrict__ y) {

    extern __shared__ __align__(1024) char smem[];
    __shared__ unsigned s_mask;   // bitmask of batches this block must apply
    const int tid = threadIdx.x;

    if (blockIdx.x == 160) {
        build_p2_body(smem, eiw, ew, E);
        __syncthreads();
        if (tid == 0) s_mask = 0;
        __syncthreads();
        if (tid < 32) {
            __threadfence();
            unsigned old = atomicAdd(&g_cnt[tid], 1u);
            if (((old + 1) % ARRIVALS) == 0) atomicOr(&s_mask, 1u << tid);
        }
        __syncthreads();
        unsigned mask = s_mask;
        if (mask) {
            __threadfence();
            for (int b = 0; b < 32; b++)
                if (mask & (1u << b)) apply_batch(smem, b, bias, y);
        }
        return;
    }

    const uint32_t sb = smem_u32(smem);
    const int wid = tid >> 5;
    const int lane = tid & 31;

    const int mt = blockIdx.x & 31;       // batch 0..31
    const int ks = blockIdx.x >> 5;       // 0..4
    const int m_base = mt * MT;
    const int k0 = ks * KSLICE;

    // loader roles
    const int xrow = tid >> 2, xq = (tid & 3) * 4;      // X: 64r x 16k
    const int brow = tid >> 1, bq = (tid & 1) * 8;      // W: 128r x 16k
    const float* xp = X + (size_t)(m_base + xrow) * GK + k0 + xq;
    const float* wp = W + (size_t)brow * GK + k0 + bq;
    const uint32_t xoff = (uint32_t)(xrow * 48 + xq * 2);
    const uint32_t boff = (uint32_t)(brow * 48 + bq * 2);

    // compute roles: 8 warps = 2(m) x 4(n); warp tile 32m x 32n
    const int warp_m = wid >> 2, warp_n = wid & 3;

    float acc[32];
#pragma unroll
    for (int i = 0; i < 32; i++) acc[i] = 0.0f;

    // prologue: tile 0 -> buf0 ; reg sets hold tiles 1 (set1) and 2 (set0)
    {
        float4 xv = *(const float4*)xp;
        float4 w0 = *(const float4*)wp;
        float4 w1 = *(const float4*)(wp + 4);
        uint32_t h0, h1;
        cvt_h2(xv, h0, h1); sts2(sb + xoff, h0, h1);
        cvt_h2(w0, h0, h1); sts2(sb + 3072 + boff, h0, h1);
        cvt_h2(w1, h0, h1); sts2(sb + 3072 + boff + 8, h0, h1);
    }
    float4 xr[2], wr0[2], wr1[2];
    xr[1] = *(const float4*)(xp + 16);
    wr0[1] = *(const float4*)(wp + 16);
    wr1[1] = *(const float4*)(wp + 20);
    xr[0] = *(const float4*)(xp + 32);
    wr0[0] = *(const float4*)(wp + 32);
    wr1[0] = *(const float4*)(wp + 36);
    __syncthreads();

    const uint32_t lrow = (uint32_t)(lane & 15);
    const uint32_t lkh = (uint32_t)(lane >> 4) * 16;
    const uint32_t raBase = (32u * warp_m + lrow) * 48 + lkh;
    const uint32_t rbBase = (32u * warp_n + lrow) * 48 + lkh;

    for (int t = 0; t < NKT; t++) {
        const uint32_t st = sb + (t & 1) * STAGE_BYTES;

        // load fragments from current buffer
        uint32_t Ah[2][4], Bh[2][4];
#pragma unroll
        for (int f = 0; f < 2; f++) {
            ldsm4(Ah[f], st + raBase + 16u * 48u * f);
            ldsm4(Bh[f], st + 3072 + rbBase + 16u * 48u * f);
        }

        // store tile t+1 from reg set (t+1)&1 into the other buffer
        if (t + 1 < NKT) {
            const int s = (t + 1) & 1;
            const uint32_t so = sb + s * STAGE_BYTES;
            uint32_t h0, h1;
            cvt_h2(xr[s], h0, h1);  sts2(so + xoff, h0, h1);
            cvt_h2(wr0[s], h0, h1); sts2(so + 3072 + boff, h0, h1);
            cvt_h2(wr1[s], h0, h1); sts2(so + 3072 + boff + 8, h0, h1);
        }
        // prefetch tile t+3 into the freed reg set (2-iteration LDG slack)
        if (t + 3 < NKT) {
            const int s = (t + 3) & 1;
            const int off = (t + 3) * 16;
            xr[s] = *(const float4*)(xp + off);
            wr0[s] = *(const float4*)(wp + off);
            wr1[s] = *(const float4*)(wp + off + 4);
        }
        __syncthreads();

        // mma (8 per warp)
#pragma unroll
        for (int f = 0; f < 2; f++) {
#pragma unroll
            for (int g = 0; g < 2; g++) {
                float* c0 = acc + (f * 4 + 2 * g) * 4;
                float* c1 = acc + (f * 4 + 2 * g + 1) * 4;
                mma_f16(c0, Ah[f], Bh[g][0], Bh[g][2]);
                mma_f16(c1, Ah[f], Bh[g][1], Bh[g][3]);
            }
        }
    }

    // epilogue: write Z-partial
    float* zp = g_Zp[ks];
    const int cr = lane >> 2, cc = (lane & 3) * 2;
#pragma unroll
    for (int f = 0; f < 2; f++) {
#pragma unroll
        for (int nb = 0; nb < 4; nb++) {
            const float* c = acc + (f * 4 + nb) * 4;
            int row = m_base + 32 * warp_m + 16 * f + cr;
            int col = 32 * warp_n + 8 * nb + cc;
            *(float2*)&zp[(size_t)row * GH + col] = make_float2(c[0], c[1]);
            *(float2*)&zp[(size_t)(row + 8) * GH + col] = make_float2(c[2], c[3]);
        }
    }

    // arrival + possible apply (threadfence-reduction pattern)
    __syncthreads();
    if (tid == 0) {
        __threadfence();
        unsigned old = atomicAdd(&g_cnt[mt], 1u);
        s_mask = (((old + 1) % ARRIVALS) == 0) ? 1u : 0u;
    }
    __syncthreads();
    if (s_mask) {
        __threadfence();
        apply_batch(smem, mt, bias, y);
    }
}

// ---------------------------------------------------------------------------
extern "C" void kernel_launch(void* const* d_in, const int* in_sizes, int n_in,
                              void* d_out, int out_size) {
    const float* x    = (const float*)d_in[0];
    const int*   eiw  = (const int*)d_in[1];
    const float* ew   = (const float*)d_in[2];
    const float* W    = (const float*)d_in[3];
    const float* bias = (const float*)d_in[4];
    float*       y    = (float*)d_out;

    const int E = in_sizes[1] / 2;

    static bool attr_set = false;
    if (!attr_set) {
        cudaFuncSetAttribute(fused_kernel,
                             cudaFuncAttributeMaxDynamicSharedMemorySize,
                             SMEM_DYN_BYTES);
        attr_set = true;
    }
    fused_kernel<<<161, 256, SMEM_DYN_BYTES>>>(x, W, eiw, ew, E, bias, y);
}

// round 9
// speedup vs baseline: 7.5707x; 7.5707x over previous
#include <cuda_runtime.h>
#include <cuda_fp16.h>
#include <cstdint>

// ---------------------------------------------------------------------------
// SimpleGCNNet:  Y = P^2 * X * W^T + b
//   X: (2048, 2000) fp32, W: (128, 2000), b: (128,) -> Y: (32, 64, 128)
// Kernel A (grid 161): blocks 0..159: Zp[ks] = X[batch mt] @ W^T over k-slice
//     of 400 (13 paired 16-k stages/iter), fp16 mma.sync m16n8k16.
//     block 160: build P -> P2t (dual P/Pt copies, float4 dot).
// Kernel B (grid 128 x 512 thr): Y[b,:,hq:hq+32] = P2 @ (sum Zp)[b] + bias
// ---------------------------------------------------------------------------

#define NNODE 64
#define GM 2048
#define GK 2000
#define GH 128
#define KSPLIT 5
#define KSLICE 400
#define NPAIR 13             // 13 pairs of 16-k stages (stage 25 zero-filled)
#define NSTAGE 25
#define MT 64
#define EPSW 1e-6f

// GEMM smem: 2 buffers x 2 stages x 9216 B (stage: aH 64x48B @0, bH 128x48B @3072)
#define STAGE_BYTES 9216
#define BUF_BYTES (2 * STAGE_BYTES)
#define SMEM_DYN_BYTES (2 * BUF_BYTES)   // 36864 (< 48KB default, no attr needed)

__device__ float g_P2t[NNODE * NNODE];    // transposed: [m][n]
__device__ float g_Zp[KSPLIT][GM * GH];

// ---- helpers --------------------------------------------------------------
__device__ __forceinline__ uint32_t smem_u32(const void* p) {
    uint32_t a;
    asm("{ .reg .u64 t; cvta.to.shared.u64 t, %1; cvt.u32.u64 %0, t; }"
        : "=r"(a) : "l"(p));
    return a;
}
__device__ __forceinline__ unsigned long long pack2(float lo, float hi) {
    unsigned long long r;
    asm("mov.b64 %0, {%1, %2};" : "=l"(r) : "f"(lo), "f"(hi));
    return r;
}
__device__ __forceinline__ unsigned long long fma2(unsigned long long a,
                                                   unsigned long long b,
                                                   unsigned long long c) {
    unsigned long long d;
    asm("fma.rn.f32x2 %0, %1, %2, %3;" : "=l"(d) : "l"(a), "l"(b), "l"(c));
    return d;
}
__device__ __forceinline__ float2 unpack2(unsigned long long v) {
    float2 f;
    asm("mov.b64 {%0, %1}, %2;" : "=f"(f.x), "=f"(f.y) : "l"(v));
    return f;
}
__device__ __forceinline__ void ldsm4(uint32_t* r, uint32_t addr) {
    asm volatile("ldmatrix.sync.aligned.m8n8.x4.shared.b16 {%0,%1,%2,%3}, [%4];"
                 : "=r"(r[0]), "=r"(r[1]), "=r"(r[2]), "=r"(r[3]) : "r"(addr));
}
__device__ __forceinline__ void mma_f16(float* c, const uint32_t* a,
                                        uint32_t b0, uint32_t b1) {
    asm volatile(
        "mma.sync.aligned.m16n8k16.row.col.f32.f16.f16.f32 "
        "{%0,%1,%2,%3}, {%4,%5,%6,%7}, {%8,%9}, {%0,%1,%2,%3};"
        : "+f"(c[0]), "+f"(c[1]), "+f"(c[2]), "+f"(c[3])
        : "r"(a[0]), "r"(a[1]), "r"(a[2]), "r"(a[3]), "r"(b0), "r"(b1));
}
__device__ __forceinline__ void cvt_h2(float4 v, uint32_t& h0, uint32_t& h1) {
    asm("cvt.rn.f16x2.f32 %0, %1, %2;" : "=r"(h0) : "f"(v.y), "f"(v.x));
    asm("cvt.rn.f16x2.f32 %0, %1, %2;" : "=r"(h1) : "f"(v.w), "f"(v.z));
}
__device__ __forceinline__ void sts2(uint32_t addr, uint32_t a, uint32_t b) {
    asm volatile("st.shared.v2.b32 [%0], {%1, %2};" :: "r"(addr), "r"(a), "r"(b)
                 : "memory");
}

// ---------------------------------------------------------------------------
// build P -> P2t ; dual P/Pt copies (row stride 68 floats, conflict-free),
// P2 inner loop uses float4 x float4 dots. Scratch in dynamic smem (36864 B):
//   P @ 0 (17408), Pt @ 17408 (17408), deg @ 34816, dinv @ 35072, flag @ 35328
// ---------------------------------------------------------------------------
#define PSTR 68
__device__ void build_p2_body(char* dsm, const int* __restrict__ eiw,
                              const float* __restrict__ ew, int E) {
    float* P    = (float*)dsm;
    float* Pt   = (float*)(dsm + 17408);
    float* deg  = (float*)(dsm + 34816);
    float* dinv = (float*)(dsm + 35072);
    int*   flag = (int*)(dsm + 35328);
    const int tid = threadIdx.x;

    for (int i = tid; i < NNODE * PSTR; i += 256) { P[i] = 0.0f; Pt[i] = 0.0f; }
    if (tid < NNODE) deg[tid] = 1.0f;   // self-loop weight 1.0
    if (tid == 0) *flag = 0;
    __syncthreads();

    // dtype detect: int64 little-endian values in [0,64) -> odd words == 0
    if (tid < 64) {
        if (eiw[2 * tid + 1] != 0) atomicOr(flag, 1);
    }
    __syncthreads();
    const bool is64 = (*flag == 0);
    const int stride = is64 ? 2 : 1;
    const int dst_base = is64 ? 2 * E : E;

    for (int e = tid; e < E; e += 256) {
        float w = ew[e];
        if (w <= 0.0f) w = EPSW;
        atomicAdd(&deg[eiw[dst_base + e * stride] & (NNODE - 1)], w);
    }
    __syncthreads();
    if (tid < NNODE) {
        float d = deg[tid];
        dinv[tid] = (d > 0.0f) ? rsqrtf(d) : 0.0f;
    }
    __syncthreads();
    for (int e = tid; e < E; e += 256) {
        float w = ew[e];
        if (w <= 0.0f) w = EPSW;
        int s = eiw[e * stride] & (NNODE - 1);
        int d = eiw[dst_base + e * stride] & (NNODE - 1);
        float v = dinv[s] * w * dinv[d];
        atomicAdd(&P[d * PSTR + s], v);
        atomicAdd(&Pt[s * PSTR + d], v);
    }
    if (tid < NNODE) {
        float v = dinv[tid] * dinv[tid];
        atomicAdd(&P[tid * PSTR + tid], v);
        atomicAdd(&Pt[tid * PSTR + tid], v);
    }
    __syncthreads();

    // P2[r][c] = dot(P[r,:], Pt[c,:]) -> g_P2t[c*64 + r]
    const int r = tid >> 2;
    const int cb = tid & 3;
#pragma unroll
    for (int j = 0; j < 16; j++) {
        int c = cb + 4 * j;
        float acc = 0.0f;
#pragma unroll
        for (int m = 0; m < NNODE; m += 4) {
            float4 a = *(const float4*)&P[r * PSTR + m];
            float4 bt = *(const float4*)&Pt[c * PSTR + m];
            acc += a.x * bt.x + a.y * bt.y + a.z * bt.z + a.w * bt.w;
        }
        g_P2t[c * NNODE + r] = acc;
    }
}

// ---------------------------------------------------------------------------
// Kernel A: fp16 mma GEMM partials (paired k-stages) + P2 build
// ---------------------------------------------------------------------------
__global__ __launch_bounds__(256) void gemm_build_kernel(
    const float* __restrict__ X, const float* __restrict__ W,
    const int* __restrict__ eiw, const float* __restrict__ ew, int E) {

    extern __shared__ __align__(1024) char smem[];

    if (blockIdx.x == 160) { build_p2_body(smem, eiw, ew, E); return; }

    const uint32_t sb = smem_u32(smem);
    const int tid = threadIdx.x;
    const int wid = tid >> 5;
    const int lane = tid & 31;

    const int mt = blockIdx.x & 31;       // batch 0..31
    const int ks = blockIdx.x >> 5;       // 0..4
    const int m_base = mt * MT;
    const int k0 = ks * KSLICE;

    // loader roles (per 16-k stage: X 1 float4/thread, W 2 float4/thread)
    const int xrow = tid >> 2, xq = (tid & 3) * 4;
    const int brow = tid >> 1, bq = (tid & 1) * 8;
    const float* xp = X + (size_t)(m_base + xrow) * GK + k0 + xq;
    const float* wp = W + (size_t)brow * GK + k0 + bq;
    const uint32_t xoff = (uint32_t)(xrow * 48 + xq * 2);
    const uint32_t boff = (uint32_t)(brow * 48 + bq * 2);

    // compute roles: 8 warps = 2(m) x 4(n); warp tile 32m x 32n
    const int warp_m = wid >> 2, warp_n = wid & 3;

    float acc[32];
#pragma unroll
    for (int i = 0; i < 32; i++) acc[i] = 0.0f;

    const float4 fz = make_float4(0.f, 0.f, 0.f, 0.f);

    // store one 16-k stage (already in regs) into a stage slot
    auto stsStage = [&](uint32_t stAddr, float4 xv, float4 w0, float4 w1) {
        uint32_t h0, h1;
        cvt_h2(xv, h0, h1); sts2(stAddr + xoff, h0, h1);
        cvt_h2(w0, h0, h1); sts2(stAddr + 3072 + boff, h0, h1);
        cvt_h2(w1, h0, h1); sts2(stAddr + 3072 + boff + 8, h0, h1);
    };

    // prologue: pair 0 (stages 0,1) -> buf0 directly
    stsStage(sb, *(const float4*)xp, *(const float4*)wp, *(const float4*)(wp + 4));
    stsStage(sb + STAGE_BYTES, *(const float4*)(xp + 16),
             *(const float4*)(wp + 16), *(const float4*)(wp + 20));

    // reg sets: set[s] holds pair for buffer s; stage g valid iff g < 25
    float4 xr[2][2], wr0[2][2], wr1[2][2];
#pragma unroll
    for (int pre = 1; pre <= 2; pre++) {
        const int s = pre & 1;
#pragma unroll
        for (int st = 0; st < 2; st++) {
            int g = 2 * pre + st;
            bool v = (g < NSTAGE);
            int off = g * 16;
            xr[s][st]  = v ? *(const float4*)(xp + off) : fz;
            wr0[s][st] = v ? *(const float4*)(wp + off) : fz;
            wr1[s][st] = v ? *(const float4*)(wp + off + 4) : fz;
        }
    }
    __syncthreads();

    const uint32_t lrow = (uint32_t)(lane & 15);
    const uint32_t lkh = (uint32_t)(lane >> 4) * 16;
    const uint32_t raBase = (32u * warp_m + lrow) * 48 + lkh;
    const uint32_t rbBase = (32u * warp_n + lrow) * 48 + lkh + 3072;

    for (int t = 0; t < NPAIR; t++) {
        const uint32_t bufA = sb + (t & 1) * BUF_BYTES;

        // load fragments: 2 stages x (2 A + 2 B) ldsm4
        uint32_t Ah[2][2][4], Bh[2][2][4];
#pragma unroll
        for (int st = 0; st < 2; st++) {
            const uint32_t stA = bufA + st * STAGE_BYTES;
#pragma unroll
            for (int f = 0; f < 2; f++) {
                ldsm4(Ah[st][f], stA + raBase + 768u * f);
                ldsm4(Bh[st][f], stA + rbBase + 768u * f);
            }
        }

        // store pair t+1 (in reg set (t+1)&1) into the other buffer
        if (t + 1 < NPAIR) {
            const int s = (t + 1) & 1;
            const uint32_t so = sb + s * BUF_BYTES;
            stsStage(so, xr[s][0], wr0[s][0], wr1[s][0]);
            stsStage(so + STAGE_BYTES, xr[s][1], wr0[s][1], wr1[s][1]);
        }
        // prefetch pair t+3 into the freed reg set
        if (t + 3 < NPAIR) {
            const int s = (t + 3) & 1;
#pragma unroll
            for (int st = 0; st < 2; st++) {
                int g = 2 * (t + 3) + st;
                bool v = (g < NSTAGE);
                int off = g * 16;
                xr[s][st]  = v ? *(const float4*)(xp + off) : fz;
                wr0[s][st] = v ? *(const float4*)(wp + off) : fz;
                wr1[s][st] = v ? *(const float4*)(wp + off + 4) : fz;
            }
        }
        __syncthreads();

        // mma: 16 per warp (2 stages x 2 f x 2 g x 2)
#pragma unroll
        for (int st = 0; st < 2; st++) {
#pragma unroll
            for (int f = 0; f < 2; f++) {
#pragma unroll
                for (int g = 0; g < 2; g++) {
                    float* c0 = acc + (f * 4 + 2 * g) * 4;
                    float* c1 = acc + (f * 4 + 2 * g + 1) * 4;
                    mma_f16(c0, Ah[st][f], Bh[st][g][0], Bh[st][g][2]);
                    mma_f16(c1, Ah[st][f], Bh[st][g][1], Bh[st][g][3]);
                }
            }
        }
    }

    // epilogue: write Z-partial
    float* zp = g_Zp[ks];
    const int cr = lane >> 2, cc = (lane & 3) * 2;
#pragma unroll
    for (int f = 0; f < 2; f++) {
#pragma unroll
        for (int nb = 0; nb < 4; nb++) {
            const float* c = acc + (f * 4 + nb) * 4;
            int row = m_base + 32 * warp_m + 16 * f + cr;
            int col = 32 * warp_n + 8 * nb + cc;
            *(float2*)&zp[(size_t)row * GH + col] = make_float2(c[0], c[1]);
            *(float2*)&zp[(size_t)(row + 8) * GH + col] = make_float2(c[2], c[3]);
        }
    }
}

// ---------------------------------------------------------------------------
// Kernel B: Y[b,:,hq:hq+32] = P2 @ (sum_s Zp[s])[b,:,hq:hq+32] + bias
// grid 128 = 32 batches x 4 h-quarters ; 512 threads
// ---------------------------------------------------------------------------
__global__ __launch_bounds__(512) void apply_p2_kernel(
    const float* __restrict__ bias, float* __restrict__ y) {
    __shared__ __align__(16) float P2t[NNODE * NNODE];  // [m][n] 16 KB
    __shared__ __align__(16) float Zs[NNODE * 32];      // [m][hc] 8 KB
    const int b = blockIdx.x >> 2;
    const int hq = (blockIdx.x & 3) * 32;
    const int tid = threadIdx.x;

    for (int i = tid; i < NNODE * NNODE; i += 512)
        P2t[i] = g_P2t[i];

    {   // sum 5 Z-partials: 64 rows x 32 cols = 512 float4, one per thread
        int m = tid >> 3;
        int c4 = (tid & 7) * 4;
        const float* src = &g_Zp[0][((size_t)b * NNODE + m) * GH + hq + c4];
        float4 s = *(const float4*)src;
#pragma unroll
        for (int si = 1; si < KSPLIT; si++) {
            float4 v = *(const float4*)(src + (size_t)si * GM * GH);
            s.x += v.x; s.y += v.y; s.z += v.z; s.w += v.w;
        }
        *(float4*)&Zs[m * 32 + c4] = s;
    }
    __syncthreads();

    const int hp = tid & 15;          // h-pair within quarter
    const int n0 = (tid >> 4) * 2;    // 2 output rows per thread

    unsigned long long acc0, acc1;
    float2 bv = *(const float2*)(bias + hq + 2 * hp);
    acc0 = acc1 = pack2(bv.x, bv.y);

#pragma unroll 8
    for (int m = 0; m < NNODE; m++) {
        unsigned long long z = *(const unsigned long long*)&Zs[m * 32 + 2 * hp];
        float2 p = *(const float2*)&P2t[m * NNODE + n0];
        acc0 = fma2(pack2(p.x, p.x), z, acc0);
        acc1 = fma2(pack2(p.y, p.y), z, acc1);
    }

    float* yb = y + ((size_t)b * NNODE + n0) * GH + hq + 2 * hp;
    float2 v0 = unpack2(acc0), v1 = unpack2(acc1);
    *(float2*)yb = v0;
    *(float2*)(yb + GH) = v1;
}

// ---------------------------------------------------------------------------
extern "C" void kernel_launch(void* const* d_in, const int* in_sizes, int n_in,
                              void* d_out, int out_size) {
    const float* x    = (const float*)d_in[0];
    const int*   eiw  = (const int*)d_in[1];
    const float* ew   = (const float*)d_in[2];
    const float* W    = (const float*)d_in[3];
    const float* bias = (const float*)d_in[4];
    float*       y    = (float*)d_out;

    const int E = in_sizes[1] / 2;

    gemm_build_kernel<<<161, 256, SMEM_DYN_BYTES>>>(x, W, eiw, ew, E);
    apply_p2_kernel<<<128, 512>>>(bias, y);
}